// round 1
// baseline (speedup 1.0000x reference)
#include <cuda_runtime.h>
#include <math.h>

#define N_TOK 16384
#define D_DIM 256
#define BM 128
#define BN 128
#define BK 16
#define TM 8
#define TN 8
#define SHIFT 64.0f

// Scratch (device globals: allocation-free per harness rules)
__device__ float g_row_sum[N_TOK];
__device__ float g_col_sum[N_TOK];
__device__ float g_diag[N_TOK];

__global__ void infonce_init_kernel() {
    int i = blockIdx.x * blockDim.x + threadIdx.x;
    if (i < N_TOK) {
        g_row_sum[i] = 0.0f;
        g_col_sum[i] = 0.0f;
    }
}

// Fused tiled GEMM + exp + row/col partial-sum scatter.
// A = image_emb [N, D] (rows of logits), B = text_emb [N, D] (cols of logits).
__global__ __launch_bounds__(256, 2)
void infonce_gemm_exp_kernel(const float* __restrict__ A,
                             const float* __restrict__ B) {
    __shared__ float As[BK][BM + 4];
    __shared__ float Bs[BK][BN + 4];
    __shared__ float s_col[BN];

    const int bi = blockIdx.y;
    const int bj = blockIdx.x;
    const int tid = threadIdx.x;
    const int tx = tid & 15;   // 0..15 -> 8 output cols each
    const int ty = tid >> 4;   // 0..15 -> 8 output rows each

    float acc[TM][TN];
#pragma unroll
    for (int i = 0; i < TM; i++)
#pragma unroll
        for (int j = 0; j < TN; j++) acc[i][j] = 0.0f;

    const float* Ab = A + (size_t)bi * BM * D_DIM;
    const float* Bb = B + (size_t)bj * BN * D_DIM;

    for (int kt = 0; kt < D_DIM; kt += BK) {
        // 128 rows x 16 cols = 512 float4 per operand; 2 per thread
#pragma unroll
        for (int l = 0; l < 2; l++) {
            int idx = tid + l * 256;       // 0..511
            int m   = idx >> 2;            // row in tile
            int c4  = idx & 3;             // float4 slot within 16 cols
            float4 a = *(const float4*)(Ab + (size_t)m * D_DIM + kt + c4 * 4);
            As[c4 * 4 + 0][m] = a.x;
            As[c4 * 4 + 1][m] = a.y;
            As[c4 * 4 + 2][m] = a.z;
            As[c4 * 4 + 3][m] = a.w;
            float4 b = *(const float4*)(Bb + (size_t)m * D_DIM + kt + c4 * 4);
            Bs[c4 * 4 + 0][m] = b.x;
            Bs[c4 * 4 + 1][m] = b.y;
            Bs[c4 * 4 + 2][m] = b.z;
            Bs[c4 * 4 + 3][m] = b.w;
        }
        __syncthreads();

#pragma unroll
        for (int k = 0; k < BK; k++) {
            float rm[TM], rn[TN];
#pragma unroll
            for (int i = 0; i < TM; i++) rm[i] = As[k][ty * TM + i];
#pragma unroll
            for (int j = 0; j < TN; j++) rn[j] = Bs[k][tx * TN + j];
#pragma unroll
            for (int i = 0; i < TM; i++)
#pragma unroll
                for (int j = 0; j < TN; j++)
                    acc[i][j] = fmaf(rm[i], rn[j], acc[i][j]);
        }
        __syncthreads();
    }

    // Diagonal capture (raw logits) before exp overwrite.
    if (bi == bj && tx == ty) {
#pragma unroll
        for (int i = 0; i < TM; i++)
            g_diag[bi * BM + ty * TM + i] = acc[i][i];
    }

    // exp(l - SHIFT); accumulate row/col partials.
    float rsum[TM], csum[TN];
#pragma unroll
    for (int i = 0; i < TM; i++) rsum[i] = 0.0f;
#pragma unroll
    for (int j = 0; j < TN; j++) csum[j] = 0.0f;

#pragma unroll
    for (int i = 0; i < TM; i++) {
#pragma unroll
        for (int j = 0; j < TN; j++) {
            float e = __expf(acc[i][j] - SHIFT);
            rsum[i] += e;
            csum[j] += e;
        }
    }

    // Row sums: reduce across the 16 tx lanes (width-16 shuffle; lanes 0..15
    // and 16..31 of each warp are two independent ty groups).
#pragma unroll
    for (int i = 0; i < TM; i++) {
        float r = rsum[i];
#pragma unroll
        for (int off = 8; off > 0; off >>= 1)
            r += __shfl_down_sync(0xffffffffu, r, off, 16);
        if (tx == 0)
            atomicAdd(&g_row_sum[bi * BM + ty * TM + i], r);
    }

    // Col sums: reduce across ty (spans warps) via shared atomics.
    if (tid < BN) s_col[tid] = 0.0f;
    __syncthreads();
#pragma unroll
    for (int j = 0; j < TN; j++)
        atomicAdd(&s_col[tx * TN + j], csum[j]);
    __syncthreads();
    if (tid < BN)
        atomicAdd(&g_col_sum[bj * BN + tid], s_col[tid]);
}

__global__ void infonce_finalize_kernel(float* out) {
    __shared__ double s[256];
    int tid = threadIdx.x;
    double acc = 0.0;
    for (int i = tid; i < N_TOK; i += 256) {
        double lse_r = (double)logf(g_row_sum[i]) + (double)SHIFT;
        double lse_c = (double)logf(g_col_sum[i]) + (double)SHIFT;
        acc += 0.5 * (lse_r + lse_c) - (double)g_diag[i];
    }
    s[tid] = acc;
    __syncthreads();
    for (int st = 128; st > 0; st >>= 1) {
        if (tid < st) s[tid] += s[tid + st];
        __syncthreads();
    }
    if (tid == 0) out[0] = (float)(s[0] / (double)N_TOK);
}

extern "C" void kernel_launch(void* const* d_in, const int* in_sizes, int n_in,
                              void* d_out, int out_size) {
    const float* image_emb = (const float*)d_in[0];
    const float* text_emb  = (const float*)d_in[1];
    float* out = (float*)d_out;

    infonce_init_kernel<<<32, 512>>>();
    dim3 grid(N_TOK / BN, N_TOK / BM);
    infonce_gemm_exp_kernel<<<grid, 256>>>(image_emb, text_emb);
    infonce_finalize_kernel<<<1, 256>>>(out);
}

// round 2
// speedup vs baseline: 1.0010x; 1.0010x over previous
#include <cuda_runtime.h>
#include <math.h>

#define N_TOK 16384
#define D_DIM 256
#define BM 128
#define BN 128
#define BK 16
#define TM 8
#define TN 8
#define SHIFT 64.0f

// Scratch (device globals: allocation-free per harness rules)
__device__ float g_row_sum[N_TOK];
__device__ float g_col_sum[N_TOK];
__device__ float g_diag[N_TOK];

__global__ void infonce_init_kernel() {
    int i = blockIdx.x * blockDim.x + threadIdx.x;
    if (i < N_TOK) {
        g_row_sum[i] = 0.0f;
        g_col_sum[i] = 0.0f;
    }
}

// Fused tiled GEMM + exp + row/col partial-sum scatter.
// A = image_emb [N, D] (rows of logits), B = text_emb [N, D] (cols of logits).
__global__ __launch_bounds__(256, 2)
void infonce_gemm_exp_kernel(const float* __restrict__ A,
                             const float* __restrict__ B) {
    __shared__ float As[BK][BM + 4];
    __shared__ float Bs[BK][BN + 4];
    __shared__ float s_col[BN];

    const int bi = blockIdx.y;
    const int bj = blockIdx.x;
    const int tid = threadIdx.x;
    const int tx = tid & 15;   // 0..15 -> 8 output cols each
    const int ty = tid >> 4;   // 0..15 -> 8 output rows each

    float acc[TM][TN];
#pragma unroll
    for (int i = 0; i < TM; i++)
#pragma unroll
        for (int j = 0; j < TN; j++) acc[i][j] = 0.0f;

    const float* Ab = A + (size_t)bi * BM * D_DIM;
    const float* Bb = B + (size_t)bj * BN * D_DIM;

    for (int kt = 0; kt < D_DIM; kt += BK) {
        // 128 rows x 16 cols = 512 float4 per operand; 2 per thread
#pragma unroll
        for (int l = 0; l < 2; l++) {
            int idx = tid + l * 256;       // 0..511
            int m   = idx >> 2;            // row in tile
            int c4  = idx & 3;             // float4 slot within 16 cols
            float4 a = *(const float4*)(Ab + (size_t)m * D_DIM + kt + c4 * 4);
            As[c4 * 4 + 0][m] = a.x;
            As[c4 * 4 + 1][m] = a.y;
            As[c4 * 4 + 2][m] = a.z;
            As[c4 * 4 + 3][m] = a.w;
            float4 b = *(const float4*)(Bb + (size_t)m * D_DIM + kt + c4 * 4);
            Bs[c4 * 4 + 0][m] = b.x;
            Bs[c4 * 4 + 1][m] = b.y;
            Bs[c4 * 4 + 2][m] = b.z;
            Bs[c4 * 4 + 3][m] = b.w;
        }
        __syncthreads();

#pragma unroll
        for (int k = 0; k < BK; k++) {
            float rm[TM], rn[TN];
#pragma unroll
            for (int i = 0; i < TM; i++) rm[i] = As[k][ty * TM + i];
#pragma unroll
            for (int j = 0; j < TN; j++) rn[j] = Bs[k][tx * TN + j];
#pragma unroll
            for (int i = 0; i < TM; i++)
#pragma unroll
                for (int j = 0; j < TN; j++)
                    acc[i][j] = fmaf(rm[i], rn[j], acc[i][j]);
        }
        __syncthreads();
    }

    // Diagonal capture (raw logits) before exp overwrite.
    if (bi == bj && tx == ty) {
#pragma unroll
        for (int i = 0; i < TM; i++)
            g_diag[bi * BM + ty * TM + i] = acc[i][i];
    }

    // exp(l - SHIFT); accumulate row/col partials.
    float rsum[TM], csum[TN];
#pragma unroll
    for (int i = 0; i < TM; i++) rsum[i] = 0.0f;
#pragma unroll
    for (int j = 0; j < TN; j++) csum[j] = 0.0f;

#pragma unroll
    for (int i = 0; i < TM; i++) {
#pragma unroll
        for (int j = 0; j < TN; j++) {
            float e = __expf(acc[i][j] - SHIFT);
            rsum[i] += e;
            csum[j] += e;
        }
    }

    // Row sums: reduce across the 16 tx lanes (width-16 shuffle; lanes 0..15
    // and 16..31 of each warp are two independent ty groups).
#pragma unroll
    for (int i = 0; i < TM; i++) {
        float r = rsum[i];
#pragma unroll
        for (int off = 8; off > 0; off >>= 1)
            r += __shfl_down_sync(0xffffffffu, r, off, 16);
        if (tx == 0)
            atomicAdd(&g_row_sum[bi * BM + ty * TM + i], r);
    }

    // Col sums: reduce across ty (spans warps) via shared atomics.
    if (tid < BN) s_col[tid] = 0.0f;
    __syncthreads();
#pragma unroll
    for (int j = 0; j < TN; j++)
        atomicAdd(&s_col[tx * TN + j], csum[j]);
    __syncthreads();
    if (tid < BN)
        atomicAdd(&g_col_sum[bj * BN + tid], s_col[tid]);
}

__global__ void infonce_finalize_kernel(float* out) {
    __shared__ double s[256];
    int tid = threadIdx.x;
    double acc = 0.0;
    for (int i = tid; i < N_TOK; i += 256) {
        double lse_r = (double)logf(g_row_sum[i]) + (double)SHIFT;
        double lse_c = (double)logf(g_col_sum[i]) + (double)SHIFT;
        acc += 0.5 * (lse_r + lse_c) - (double)g_diag[i];
    }
    s[tid] = acc;
    __syncthreads();
    for (int st = 128; st > 0; st >>= 1) {
        if (tid < st) s[tid] += s[tid + st];
        __syncthreads();
    }
    if (tid == 0) out[0] = (float)(s[0] / (double)N_TOK);
}

extern "C" void kernel_launch(void* const* d_in, const int* in_sizes, int n_in,
                              void* d_out, int out_size) {
    const float* image_emb = (const float*)d_in[0];
    const float* text_emb  = (const float*)d_in[1];
    float* out = (float*)d_out;

    infonce_init_kernel<<<32, 512>>>();
    dim3 grid(N_TOK / BN, N_TOK / BM);
    infonce_gemm_exp_kernel<<<grid, 256>>>(image_emb, text_emb);
    infonce_finalize_kernel<<<1, 256>>>(out);
}

// round 4
// speedup vs baseline: 6.7250x; 6.7183x over previous
#include <cuda_runtime.h>
#include <cuda_bf16.h>
#include <cstdint>
#include <math.h>

#define NT 16384
#define DD 256
#define SHIFT 64.0f

__device__ float g_row_sum[NT];
__device__ float g_col_sum[NT];
__device__ float g_diag[NT];
__device__ __nv_bfloat16 g_Abf[NT * DD];
__device__ __nv_bfloat16 g_Bbf[NT * DD];

__device__ __forceinline__ uint32_t smem_u32(const void* p) {
    uint32_t a;
    asm("{ .reg .u64 t; cvta.to.shared.u64 t, %1; cvt.u32.u64 %0, t; }" : "=r"(a) : "l"(p));
    return a;
}

__global__ void infonce_init_kernel() {
    int i = blockIdx.x * blockDim.x + threadIdx.x;
    if (i < NT) { g_row_sum[i] = 0.0f; g_col_sum[i] = 0.0f; }
}

// fp32 -> bf16 row-major copies of both inputs.
__global__ void infonce_prep_kernel(const float* __restrict__ A, const float* __restrict__ B) {
    int i8 = blockIdx.x * blockDim.x + threadIdx.x;
    if (i8 >= NT * DD / 8) return;
    size_t base = (size_t)i8 * 8;
    const float4* a4 = (const float4*)(A + base);
    const float4* b4 = (const float4*)(B + base);
    float4 a0 = a4[0], a1 = a4[1];
    float4 b0 = b4[0], b1 = b4[1];
    uint4 ua, ub;
    ((__nv_bfloat162*)&ua)[0] = __floats2bfloat162_rn(a0.x, a0.y);
    ((__nv_bfloat162*)&ua)[1] = __floats2bfloat162_rn(a0.z, a0.w);
    ((__nv_bfloat162*)&ua)[2] = __floats2bfloat162_rn(a1.x, a1.y);
    ((__nv_bfloat162*)&ua)[3] = __floats2bfloat162_rn(a1.z, a1.w);
    ((__nv_bfloat162*)&ub)[0] = __floats2bfloat162_rn(b0.x, b0.y);
    ((__nv_bfloat162*)&ub)[1] = __floats2bfloat162_rn(b0.z, b0.w);
    ((__nv_bfloat162*)&ub)[2] = __floats2bfloat162_rn(b1.x, b1.y);
    ((__nv_bfloat162*)&ub)[3] = __floats2bfloat162_rn(b1.z, b1.w);
    ((uint4*)g_Abf)[i8] = ua;
    ((uint4*)g_Bbf)[i8] = ub;
}

// Exact fp32 diagonal.
__global__ void infonce_diag_kernel(const float* __restrict__ A, const float* __restrict__ B) {
    int gw = (blockIdx.x * blockDim.x + threadIdx.x) >> 5;
    int lid = threadIdx.x & 31;
    if (gw >= NT) return;
    const float4* a = (const float4*)(A + (size_t)gw * DD);
    const float4* b = (const float4*)(B + (size_t)gw * DD);
    float s = 0.0f;
    float4 x = a[lid], y = b[lid];
    s += x.x * y.x + x.y * y.y + x.z * y.z + x.w * y.w;
    x = a[lid + 32]; y = b[lid + 32];
    s += x.x * y.x + x.y * y.y + x.z * y.z + x.w * y.w;
#pragma unroll
    for (int o = 16; o > 0; o >>= 1) s += __shfl_down_sync(0xffffffffu, s, o);
    if (lid == 0) g_diag[gw] = s;
}

// Fused bf16 mma.sync GEMM + exp + row/col sum scatter.
// Tile: 128x128 per CTA, 8 warps of 64x32, K staged 64 at a time, double buffered.
__global__ void __launch_bounds__(256, 2) infonce_mma_kernel() {
    extern __shared__ char dynsmem[];
    const uint32_t sb = smem_u32(dynsmem);
    const int tid = threadIdx.x;
    const int wid = tid >> 5, lane = tid & 31;
    const int bi = blockIdx.y, bj = blockIdx.x;
    const int warp_m = wid & 1;      // 2 x 64 rows
    const int warp_n = wid >> 1;     // 4 x 32 cols

    const __nv_bfloat16* Abase = g_Abf + (size_t)bi * 128 * DD;
    const __nv_bfloat16* Bbase = g_Bbf + (size_t)bj * 128 * DD;

    float acc[4][4][4];
#pragma unroll
    for (int mt = 0; mt < 4; mt++)
#pragma unroll
        for (int nt = 0; nt < 4; nt++)
#pragma unroll
            for (int r = 0; r < 4; r++) acc[mt][nt][r] = 0.0f;

    // ldmatrix per-lane address precompute.
    // A x4 (per mt): q0:(m0-7,c0) q1:(m8-15,c0) q2:(m0-7,c1) q3:(m8-15,c1)
    // B x4 (per g):  q0:(n0-7,c0) q1:(n0-7,c1) q2:(n8-15,c0) q3:(n8-15,c1)
    const int rl = lane & 7, q = lane >> 3;
    const uint32_t qa_ch = (uint32_t)(q >> 1);
    const uint32_t qb_ch = (uint32_t)(q & 1);
    uint32_t aRel[4], aX7[4];
#pragma unroll
    for (int mt = 0; mt < 4; mt++) {
        int row = warp_m * 64 + mt * 16 + rl + (q & 1) * 8;
        aRel[mt] = (uint32_t)(row * 128);
        aX7[mt] = (uint32_t)(row & 7);
    }
    uint32_t bRel[2], bX7[2];
#pragma unroll
    for (int g = 0; g < 2; g++) {
        int rown = warp_n * 32 + g * 16 + rl + ((q >> 1) & 1) * 8;
        bRel[g] = (uint32_t)(rown * 128);
        bX7[g] = (uint32_t)(rown & 7);
    }

    // cp.async staging: 2048 16B chunks per K-slab (A:1024, B:1024), 8/thread.
    auto prefetch = [&](int kt, int buf) {
#pragma unroll
        for (int t = 0; t < 8; t++) {
            int id = tid + t * 256;
            int isB = id >> 10;
            int idx = id & 1023;
            int row = idx >> 3, c = idx & 7;
            const __nv_bfloat16* src =
                (isB ? Bbase : Abase) + (size_t)row * DD + kt * 64 + c * 8;
            uint32_t dst = sb + buf * 32768 + isB * 16384 + row * 128 +
                           (((uint32_t)c ^ (uint32_t)(row & 7)) << 4);
            asm volatile("cp.async.ca.shared.global [%0], [%1], 16;"
                         :: "r"(dst), "l"(__cvta_generic_to_global(src)) : "memory");
        }
        asm volatile("cp.async.commit_group;" ::: "memory");
    };

    prefetch(0, 0);
    int buf = 0;
#pragma unroll
    for (int kt = 0; kt < 4; kt++) {
        if (kt < 3) {
            prefetch(kt + 1, buf ^ 1);
            asm volatile("cp.async.wait_group 1;" ::: "memory");
        } else {
            asm volatile("cp.async.wait_group 0;" ::: "memory");
        }
        __syncthreads();

        const uint32_t bufA = sb + buf * 32768;
        const uint32_t bufB = bufA + 16384;
#pragma unroll
        for (int ks = 0; ks < 4; ks++) {
            uint32_t a[4][4], b[2][4];
#pragma unroll
            for (int mt = 0; mt < 4; mt++) {
                uint32_t addr = bufA + aRel[mt] +
                                ((((uint32_t)(2 * ks) + qa_ch) ^ aX7[mt]) << 4);
                asm volatile("ldmatrix.sync.aligned.m8n8.x4.shared.b16 {%0,%1,%2,%3}, [%4];"
                             : "=r"(a[mt][0]), "=r"(a[mt][1]), "=r"(a[mt][2]), "=r"(a[mt][3])
                             : "r"(addr));
            }
#pragma unroll
            for (int g = 0; g < 2; g++) {
                uint32_t addr = bufB + bRel[g] +
                                ((((uint32_t)(2 * ks) + qb_ch) ^ bX7[g]) << 4);
                asm volatile("ldmatrix.sync.aligned.m8n8.x4.shared.b16 {%0,%1,%2,%3}, [%4];"
                             : "=r"(b[g][0]), "=r"(b[g][1]), "=r"(b[g][2]), "=r"(b[g][3])
                             : "r"(addr));
            }
#pragma unroll
            for (int mt = 0; mt < 4; mt++) {
#pragma unroll
                for (int nt = 0; nt < 4; nt++) {
                    uint32_t b0 = b[nt >> 1][(nt & 1) * 2];
                    uint32_t b1 = b[nt >> 1][(nt & 1) * 2 + 1];
                    asm volatile(
                        "mma.sync.aligned.m16n8k16.row.col.f32.bf16.bf16.f32 "
                        "{%0,%1,%2,%3}, {%4,%5,%6,%7}, {%8,%9}, {%0,%1,%2,%3};"
                        : "+f"(acc[mt][nt][0]), "+f"(acc[mt][nt][1]),
                          "+f"(acc[mt][nt][2]), "+f"(acc[mt][nt][3])
                        : "r"(a[mt][0]), "r"(a[mt][1]), "r"(a[mt][2]), "r"(a[mt][3]),
                          "r"(b0), "r"(b1));
                }
            }
        }
        __syncthreads();
        buf ^= 1;
    }

    // Epilogue: exp + row/col reductions.
    // acc reg layout: c0=(r, c), c1=(r, c+1), c2=(r+8, c), c3=(r+8, c+1)
    // with r = mt*16 + lane/4, c = nt*8 + 2*(lane%4) (warp-relative).
    float csl[4], csh[4];
#pragma unroll
    for (int nt = 0; nt < 4; nt++) { csl[nt] = 0.0f; csh[nt] = 0.0f; }

#pragma unroll
    for (int mt = 0; mt < 4; mt++) {
        float rs0 = 0.0f, rs1 = 0.0f;
#pragma unroll
        for (int nt = 0; nt < 4; nt++) {
            float e0 = __expf(acc[mt][nt][0] - SHIFT);
            float e1 = __expf(acc[mt][nt][1] - SHIFT);
            float e2 = __expf(acc[mt][nt][2] - SHIFT);
            float e3 = __expf(acc[mt][nt][3] - SHIFT);
            rs0 += e0 + e1;
            rs1 += e2 + e3;
            csl[nt] += e0 + e2;
            csh[nt] += e1 + e3;
        }
        rs0 += __shfl_xor_sync(0xffffffffu, rs0, 1);
        rs0 += __shfl_xor_sync(0xffffffffu, rs0, 2);
        rs1 += __shfl_xor_sync(0xffffffffu, rs1, 1);
        rs1 += __shfl_xor_sync(0xffffffffu, rs1, 2);
        if ((lane & 3) == 0) {
            int row = bi * 128 + warp_m * 64 + mt * 16 + (lane >> 2);
            atomicAdd(&g_row_sum[row], rs0);
            atomicAdd(&g_row_sum[row + 8], rs1);
        }
    }
#pragma unroll
    for (int nt = 0; nt < 4; nt++) {
        float cl = csl[nt], ch = csh[nt];
        cl += __shfl_xor_sync(0xffffffffu, cl, 4);
        cl += __shfl_xor_sync(0xffffffffu, cl, 8);
        cl += __shfl_xor_sync(0xffffffffu, cl, 16);
        ch += __shfl_xor_sync(0xffffffffu, ch, 4);
        ch += __shfl_xor_sync(0xffffffffu, ch, 8);
        ch += __shfl_xor_sync(0xffffffffu, ch, 16);
        if (lane < 4) {
            int col = bj * 128 + warp_n * 32 + nt * 8 + 2 * lane;
            atomicAdd(&g_col_sum[col], cl);
            atomicAdd(&g_col_sum[col + 1], ch);
        }
    }
}

__global__ void infonce_finalize_kernel(float* out) {
    __shared__ double s[256];
    int tid = threadIdx.x;
    double acc = 0.0;
    for (int i = tid; i < NT; i += 256) {
        double lse_r = (double)logf(g_row_sum[i]) + (double)SHIFT;
        double lse_c = (double)logf(g_col_sum[i]) + (double)SHIFT;
        acc += 0.5 * (lse_r + lse_c) - (double)g_diag[i];
    }
    s[tid] = acc;
    __syncthreads();
    for (int st = 128; st > 0; st >>= 1) {
        if (tid < st) s[tid] += s[tid + st];
        __syncthreads();
    }
    if (tid == 0) out[0] = (float)(s[0] / (double)NT);
}

extern "C" void kernel_launch(void* const* d_in, const int* in_sizes, int n_in,
                              void* d_out, int out_size) {
    const float* image_emb = (const float*)d_in[0];
    const float* text_emb  = (const float*)d_in[1];
    float* out = (float*)d_out;

    cudaFuncSetAttribute(infonce_mma_kernel,
                         cudaFuncAttributeMaxDynamicSharedMemorySize, 65536);

    infonce_init_kernel<<<32, 512>>>();
    infonce_prep_kernel<<<(NT * DD / 8 + 255) / 256, 256>>>(image_emb, text_emb);
    infonce_diag_kernel<<<NT * 32 / 256, 256>>>(image_emb, text_emb);
    infonce_mma_kernel<<<dim3(128, 128), 256, 65536>>>();
    infonce_finalize_kernel<<<1, 256>>>(out);
}

// round 6
// speedup vs baseline: 7.4534x; 1.1083x over previous
#include <cuda_runtime.h>
#include <cuda_bf16.h>
#include <cstdint>
#include <math.h>

#define NT 16384
#define DD 256
#define SHIFT 64.0f

__device__ float g_row_sum[NT];
__device__ float g_col_sum[NT];
__device__ float g_diag[NT];
__device__ __nv_bfloat16 g_Abf[NT * DD];
__device__ __nv_bfloat16 g_Bbf[NT * DD];

__device__ __forceinline__ uint32_t smem_u32(const void* p) {
    uint32_t a;
    asm("{ .reg .u64 t; cvta.to.shared.u64 t, %1; cvt.u32.u64 %0, t; }" : "=r"(a) : "l"(p));
    return a;
}

__global__ void infonce_init_kernel() {
    int i = blockIdx.x * blockDim.x + threadIdx.x;
    if (i < NT) { g_row_sum[i] = 0.0f; g_col_sum[i] = 0.0f; }
}

// Fused: fp32 -> bf16 repack of both inputs + exact fp32 diagonal dot.
// One warp per row.
__global__ void infonce_prep_diag_kernel(const float* __restrict__ A,
                                         const float* __restrict__ B) {
    int row = (blockIdx.x * blockDim.x + threadIdx.x) >> 5;
    int lane = threadIdx.x & 31;
    if (row >= NT) return;
    const float4* a4 = (const float4*)(A + (size_t)row * DD) + 2 * lane;
    const float4* b4 = (const float4*)(B + (size_t)row * DD) + 2 * lane;
    float4 x0 = a4[0], x1 = a4[1];
    float4 y0 = b4[0], y1 = b4[1];
    uint4 ua, ub;
    ((__nv_bfloat162*)&ua)[0] = __floats2bfloat162_rn(x0.x, x0.y);
    ((__nv_bfloat162*)&ua)[1] = __floats2bfloat162_rn(x0.z, x0.w);
    ((__nv_bfloat162*)&ua)[2] = __floats2bfloat162_rn(x1.x, x1.y);
    ((__nv_bfloat162*)&ua)[3] = __floats2bfloat162_rn(x1.z, x1.w);
    ((__nv_bfloat162*)&ub)[0] = __floats2bfloat162_rn(y0.x, y0.y);
    ((__nv_bfloat162*)&ub)[1] = __floats2bfloat162_rn(y0.z, y0.w);
    ((__nv_bfloat162*)&ub)[2] = __floats2bfloat162_rn(y1.x, y1.y);
    ((__nv_bfloat162*)&ub)[3] = __floats2bfloat162_rn(y1.z, y1.w);
    ((uint4*)(g_Abf + (size_t)row * DD))[lane] = ua;
    ((uint4*)(g_Bbf + (size_t)row * DD))[lane] = ub;
    float s = x0.x * y0.x + x0.y * y0.y + x0.z * y0.z + x0.w * y0.w
            + x1.x * y1.x + x1.y * y1.y + x1.z * y1.z + x1.w * y1.w;
#pragma unroll
    for (int o = 16; o > 0; o >>= 1) s += __shfl_down_sync(0xffffffffu, s, o);
    if (lane == 0) g_diag[row] = s;
}

// Fused bf16 mma.sync GEMM + exp + row/col sum scatter.
// Tile: 128x128 per CTA, 4 warps of 64x64, K staged 64 at a time, double buffered.
__global__ void __launch_bounds__(128, 2) infonce_mma_kernel() {
    extern __shared__ char dynsmem[];
    const uint32_t sb = smem_u32(dynsmem);
    const int tid = threadIdx.x;
    const int wid = tid >> 5, lane = tid & 31;
    const int bi = blockIdx.y, bj = blockIdx.x;
    const int warp_m = wid & 1;      // 2 x 64 rows
    const int warp_n = wid >> 1;     // 2 x 64 cols

    const __nv_bfloat16* Abase = g_Abf + (size_t)bi * 128 * DD;
    const __nv_bfloat16* Bbase = g_Bbf + (size_t)bj * 128 * DD;

    float acc[4][8][4];
#pragma unroll
    for (int mt = 0; mt < 4; mt++)
#pragma unroll
        for (int nt = 0; nt < 8; nt++)
#pragma unroll
            for (int r = 0; r < 4; r++) acc[mt][nt][r] = 0.0f;

    // ldmatrix per-lane address precompute (identical layout to validated R4).
    const int rl = lane & 7, q = lane >> 3;
    const uint32_t qa_ch = (uint32_t)(q >> 1);
    const uint32_t qb_ch = (uint32_t)(q & 1);
    uint32_t aRel[4], aX7[4];
#pragma unroll
    for (int mt = 0; mt < 4; mt++) {
        int row = warp_m * 64 + mt * 16 + rl + (q & 1) * 8;
        aRel[mt] = (uint32_t)(row * 128);
        aX7[mt] = (uint32_t)(row & 7);
    }
    uint32_t bRel[4], bX7[4];
#pragma unroll
    for (int g = 0; g < 4; g++) {
        int rown = warp_n * 64 + g * 16 + rl + ((q >> 1) & 1) * 8;
        bRel[g] = (uint32_t)(rown * 128);
        bX7[g] = (uint32_t)(rown & 7);
    }

    // cp.async staging: 2048 16B chunks per K-slab (A:1024, B:1024), 16/thread.
    auto prefetch = [&](int kt, int buf) {
#pragma unroll
        for (int t = 0; t < 16; t++) {
            int id = tid + t * 128;
            int isB = id >> 10;
            int idx = id & 1023;
            int row = idx >> 3, c = idx & 7;
            const __nv_bfloat16* src =
                (isB ? Bbase : Abase) + (size_t)row * DD + kt * 64 + c * 8;
            uint32_t dst = sb + buf * 32768 + isB * 16384 + row * 128 +
                           (((uint32_t)c ^ (uint32_t)(row & 7)) << 4);
            asm volatile("cp.async.ca.shared.global [%0], [%1], 16;"
                         :: "r"(dst), "l"(__cvta_generic_to_global(src)) : "memory");
        }
        asm volatile("cp.async.commit_group;" ::: "memory");
    };

    prefetch(0, 0);
    int buf = 0;
#pragma unroll
    for (int kt = 0; kt < 4; kt++) {
        if (kt < 3) {
            prefetch(kt + 1, buf ^ 1);
            asm volatile("cp.async.wait_group 1;" ::: "memory");
        } else {
            asm volatile("cp.async.wait_group 0;" ::: "memory");
        }
        __syncthreads();

        const uint32_t bufA = sb + buf * 32768;
        const uint32_t bufB = bufA + 16384;
#pragma unroll
        for (int ks = 0; ks < 4; ks++) {
            uint32_t a[4][4], b[4][4];
#pragma unroll
            for (int mt = 0; mt < 4; mt++) {
                uint32_t addr = bufA + aRel[mt] +
                                ((((uint32_t)(2 * ks) + qa_ch) ^ aX7[mt]) << 4);
                asm volatile("ldmatrix.sync.aligned.m8n8.x4.shared.b16 {%0,%1,%2,%3}, [%4];"
                             : "=r"(a[mt][0]), "=r"(a[mt][1]), "=r"(a[mt][2]), "=r"(a[mt][3])
                             : "r"(addr));
            }
#pragma unroll
            for (int g = 0; g < 4; g++) {
                uint32_t addr = bufB + bRel[g] +
                                ((((uint32_t)(2 * ks) + qb_ch) ^ bX7[g]) << 4);
                asm volatile("ldmatrix.sync.aligned.m8n8.x4.shared.b16 {%0,%1,%2,%3}, [%4];"
                             : "=r"(b[g][0]), "=r"(b[g][1]), "=r"(b[g][2]), "=r"(b[g][3])
                             : "r"(addr));
            }
#pragma unroll
            for (int mt = 0; mt < 4; mt++) {
#pragma unroll
                for (int nt = 0; nt < 8; nt++) {
                    uint32_t b0 = b[nt >> 1][(nt & 1) * 2];
                    uint32_t b1 = b[nt >> 1][(nt & 1) * 2 + 1];
                    asm volatile(
                        "mma.sync.aligned.m16n8k16.row.col.f32.bf16.bf16.f32 "
                        "{%0,%1,%2,%3}, {%4,%5,%6,%7}, {%8,%9}, {%0,%1,%2,%3};"
                        : "+f"(acc[mt][nt][0]), "+f"(acc[mt][nt][1]),
                          "+f"(acc[mt][nt][2]), "+f"(acc[mt][nt][3])
                        : "r"(a[mt][0]), "r"(a[mt][1]), "r"(a[mt][2]), "r"(a[mt][3]),
                          "r"(b0), "r"(b1));
                }
            }
        }
        __syncthreads();
        buf ^= 1;
    }

    // Epilogue: exp + row/col reductions.
    // acc reg layout: c0=(r, c), c1=(r, c+1), c2=(r+8, c), c3=(r+8, c+1)
    // with r = mt*16 + lane/4, c = nt*8 + 2*(lane%4) (warp-relative).
    float csl[8], csh[8];
#pragma unroll
    for (int nt = 0; nt < 8; nt++) { csl[nt] = 0.0f; csh[nt] = 0.0f; }

#pragma unroll
    for (int mt = 0; mt < 4; mt++) {
        float rs0 = 0.0f, rs1 = 0.0f;
#pragma unroll
        for (int nt = 0; nt < 8; nt++) {
            float e0 = __expf(acc[mt][nt][0] - SHIFT);
            float e1 = __expf(acc[mt][nt][1] - SHIFT);
            float e2 = __expf(acc[mt][nt][2] - SHIFT);
            float e3 = __expf(acc[mt][nt][3] - SHIFT);
            rs0 += e0 + e1;
            rs1 += e2 + e3;
            csl[nt] += e0 + e2;
            csh[nt] += e1 + e3;
        }
        rs0 += __shfl_xor_sync(0xffffffffu, rs0, 1);
        rs0 += __shfl_xor_sync(0xffffffffu, rs0, 2);
        rs1 += __shfl_xor_sync(0xffffffffu, rs1, 1);
        rs1 += __shfl_xor_sync(0xffffffffu, rs1, 2);
        if ((lane & 3) == 0) {
            int row = bi * 128 + warp_m * 64 + mt * 16 + (lane >> 2);
            atomicAdd(&g_row_sum[row], rs0);
            atomicAdd(&g_row_sum[row + 8], rs1);
        }
    }
#pragma unroll
    for (int nt = 0; nt < 8; nt++) {
        float cl = csl[nt], ch = csh[nt];
        cl += __shfl_xor_sync(0xffffffffu, cl, 4);
        cl += __shfl_xor_sync(0xffffffffu, cl, 8);
        cl += __shfl_xor_sync(0xffffffffu, cl, 16);
        ch += __shfl_xor_sync(0xffffffffu, ch, 4);
        ch += __shfl_xor_sync(0xffffffffu, ch, 8);
        ch += __shfl_xor_sync(0xffffffffu, ch, 16);
        if (lane < 4) {
            int col = bj * 128 + warp_n * 64 + nt * 8 + 2 * lane;
            atomicAdd(&g_col_sum[col], cl);
            atomicAdd(&g_col_sum[col + 1], ch);
        }
    }
}

__global__ void infonce_finalize_kernel(float* out) {
    __shared__ double s[256];
    int tid = threadIdx.x;
    double acc = 0.0;
    for (int i = tid; i < NT; i += 256) {
        double lse_r = (double)logf(g_row_sum[i]) + (double)SHIFT;
        double lse_c = (double)logf(g_col_sum[i]) + (double)SHIFT;
        acc += 0.5 * (lse_r + lse_c) - (double)g_diag[i];
    }
    s[tid] = acc;
    __syncthreads();
    for (int st = 128; st > 0; st >>= 1) {
        if (tid < st) s[tid] += s[tid + st];
        __syncthreads();
    }
    if (tid == 0) out[0] = (float)(s[0] / (double)NT);
}

extern "C" void kernel_launch(void* const* d_in, const int* in_sizes, int n_in,
                              void* d_out, int out_size) {
    const float* image_emb = (const float*)d_in[0];
    const float* text_emb  = (const float*)d_in[1];
    float* out = (float*)d_out;

    cudaFuncSetAttribute(infonce_mma_kernel,
                         cudaFuncAttributeMaxDynamicSharedMemorySize, 65536);

    infonce_init_kernel<<<32, 512>>>();
    infonce_prep_diag_kernel<<<NT * 32 / 256, 256>>>(image_emb, text_emb);
    infonce_mma_kernel<<<dim3(128, 128), 128, 65536>>>();
    infonce_finalize_kernel<<<1, 256>>>(out);
}

// round 7
// speedup vs baseline: 8.8852x; 1.1921x over previous
#include <cuda_runtime.h>
#include <cuda_bf16.h>
#include <cstdint>
#include <math.h>

#define NT 16384
#define DD 256
#define SHIFT 64.0f

__device__ float g_row_sum[NT];
__device__ float g_col_sum[NT];
__device__ float g_diag[NT];
__device__ double g_acc;
__device__ __nv_bfloat16 g_Abf[NT * DD];
__device__ __nv_bfloat16 g_Bbf[NT * DD];

__device__ __forceinline__ uint32_t smem_u32(const void* p) {
    uint32_t a;
    asm("{ .reg .u64 t; cvta.to.shared.u64 t, %1; cvt.u32.u64 %0, t; }" : "=r"(a) : "l"(p));
    return a;
}

// Fused: zero accumulators + fp32 -> bf16 repack + exact fp32 diagonal dot.
// One warp per row (16384 warps).
__global__ void infonce_prep_diag_kernel(const float* __restrict__ A,
                                         const float* __restrict__ B) {
    int row = (blockIdx.x * blockDim.x + threadIdx.x) >> 5;
    int lane = threadIdx.x & 31;
    if (row >= NT) return;
    if (lane == 1) g_row_sum[row] = 0.0f;
    if (lane == 2) g_col_sum[row] = 0.0f;
    if (row == 0 && lane == 3) g_acc = 0.0;
    const float4* a4 = (const float4*)(A + (size_t)row * DD) + 2 * lane;
    const float4* b4 = (const float4*)(B + (size_t)row * DD) + 2 * lane;
    float4 x0 = a4[0], x1 = a4[1];
    float4 y0 = b4[0], y1 = b4[1];
    uint4 ua, ub;
    ((__nv_bfloat162*)&ua)[0] = __floats2bfloat162_rn(x0.x, x0.y);
    ((__nv_bfloat162*)&ua)[1] = __floats2bfloat162_rn(x0.z, x0.w);
    ((__nv_bfloat162*)&ua)[2] = __floats2bfloat162_rn(x1.x, x1.y);
    ((__nv_bfloat162*)&ua)[3] = __floats2bfloat162_rn(x1.z, x1.w);
    ((__nv_bfloat162*)&ub)[0] = __floats2bfloat162_rn(y0.x, y0.y);
    ((__nv_bfloat162*)&ub)[1] = __floats2bfloat162_rn(y0.z, y0.w);
    ((__nv_bfloat162*)&ub)[2] = __floats2bfloat162_rn(y1.x, y1.y);
    ((__nv_bfloat162*)&ub)[3] = __floats2bfloat162_rn(y1.z, y1.w);
    ((uint4*)(g_Abf + (size_t)row * DD))[lane] = ua;
    ((uint4*)(g_Bbf + (size_t)row * DD))[lane] = ub;
    float s = x0.x * y0.x + x0.y * y0.y + x0.z * y0.z + x0.w * y0.w
            + x1.x * y1.x + x1.y * y1.y + x1.z * y1.z + x1.w * y1.w;
#pragma unroll
    for (int o = 16; o > 0; o >>= 1) s += __shfl_down_sync(0xffffffffu, s, o);
    if (lane == 0) g_diag[row] = s;
}

// Fused bf16 mma.sync GEMM + exp + row/col sum scatter.
// Tile: 128x128 per CTA, 4 warps of 64x64, K staged 64 at a time, double buffered.
__global__ void __launch_bounds__(128, 2) infonce_mma_kernel() {
    extern __shared__ char dynsmem[];
    const uint32_t sb = smem_u32(dynsmem);
    const int tid = threadIdx.x;
    const int wid = tid >> 5, lane = tid & 31;
    const int bi = blockIdx.y, bj = blockIdx.x;
    const int warp_m = wid & 1;      // 2 x 64 rows
    const int warp_n = wid >> 1;     // 2 x 64 cols

    const __nv_bfloat16* Abase = g_Abf + (size_t)bi * 128 * DD;
    const __nv_bfloat16* Bbase = g_Bbf + (size_t)bj * 128 * DD;

    float acc[4][8][4];
#pragma unroll
    for (int mt = 0; mt < 4; mt++)
#pragma unroll
        for (int nt = 0; nt < 8; nt++)
#pragma unroll
            for (int r = 0; r < 4; r++) acc[mt][nt][r] = 0.0f;

    const int rl = lane & 7, q = lane >> 3;
    const uint32_t qa_ch = (uint32_t)(q >> 1);
    const uint32_t qb_ch = (uint32_t)(q & 1);
    uint32_t aRel[4], aX7[4];
#pragma unroll
    for (int mt = 0; mt < 4; mt++) {
        int row = warp_m * 64 + mt * 16 + rl + (q & 1) * 8;
        aRel[mt] = (uint32_t)(row * 128);
        aX7[mt] = (uint32_t)(row & 7);
    }
    uint32_t bRel[4], bX7[4];
#pragma unroll
    for (int g = 0; g < 4; g++) {
        int rown = warp_n * 64 + g * 16 + rl + ((q >> 1) & 1) * 8;
        bRel[g] = (uint32_t)(rown * 128);
        bX7[g] = (uint32_t)(rown & 7);
    }

    // cp.async staging via .cg (L2 only — keep L1 free for ldmatrix traffic).
    auto prefetch = [&](int kt, int buf) {
#pragma unroll
        for (int t = 0; t < 16; t++) {
            int id = tid + t * 128;
            int isB = id >> 10;
            int idx = id & 1023;
            int row = idx >> 3, c = idx & 7;
            const __nv_bfloat16* src =
                (isB ? Bbase : Abase) + (size_t)row * DD + kt * 64 + c * 8;
            uint32_t dst = sb + buf * 32768 + isB * 16384 + row * 128 +
                           (((uint32_t)c ^ (uint32_t)(row & 7)) << 4);
            asm volatile("cp.async.cg.shared.global [%0], [%1], 16;"
                         :: "r"(dst), "l"(__cvta_generic_to_global(src)) : "memory");
        }
        asm volatile("cp.async.commit_group;" ::: "memory");
    };

    prefetch(0, 0);
    int buf = 0;
#pragma unroll
    for (int kt = 0; kt < 4; kt++) {
        if (kt < 3) {
            prefetch(kt + 1, buf ^ 1);
            asm volatile("cp.async.wait_group 1;" ::: "memory");
        } else {
            asm volatile("cp.async.wait_group 0;" ::: "memory");
        }
        __syncthreads();

        const uint32_t bufA = sb + buf * 32768;
        const uint32_t bufB = bufA + 16384;
#pragma unroll
        for (int ks = 0; ks < 4; ks++) {
            uint32_t a[4][4], b[4][4];
#pragma unroll
            for (int mt = 0; mt < 4; mt++) {
                uint32_t addr = bufA + aRel[mt] +
                                ((((uint32_t)(2 * ks) + qa_ch) ^ aX7[mt]) << 4);
                asm volatile("ldmatrix.sync.aligned.m8n8.x4.shared.b16 {%0,%1,%2,%3}, [%4];"
                             : "=r"(a[mt][0]), "=r"(a[mt][1]), "=r"(a[mt][2]), "=r"(a[mt][3])
                             : "r"(addr));
            }
#pragma unroll
            for (int g = 0; g < 4; g++) {
                uint32_t addr = bufB + bRel[g] +
                                ((((uint32_t)(2 * ks) + qb_ch) ^ bX7[g]) << 4);
                asm volatile("ldmatrix.sync.aligned.m8n8.x4.shared.b16 {%0,%1,%2,%3}, [%4];"
                             : "=r"(b[g][0]), "=r"(b[g][1]), "=r"(b[g][2]), "=r"(b[g][3])
                             : "r"(addr));
            }
#pragma unroll
            for (int mt = 0; mt < 4; mt++) {
#pragma unroll
                for (int nt = 0; nt < 8; nt++) {
                    uint32_t b0 = b[nt >> 1][(nt & 1) * 2];
                    uint32_t b1 = b[nt >> 1][(nt & 1) * 2 + 1];
                    asm volatile(
                        "mma.sync.aligned.m16n8k16.row.col.f32.bf16.bf16.f32 "
                        "{%0,%1,%2,%3}, {%4,%5,%6,%7}, {%8,%9}, {%0,%1,%2,%3};"
                        : "+f"(acc[mt][nt][0]), "+f"(acc[mt][nt][1]),
                          "+f"(acc[mt][nt][2]), "+f"(acc[mt][nt][3])
                        : "r"(a[mt][0]), "r"(a[mt][1]), "r"(a[mt][2]), "r"(a[mt][3]),
                          "r"(b0), "r"(b1));
                }
            }
        }
        __syncthreads();
        buf ^= 1;
    }

    // Epilogue: exp + row/col reductions.
    float csl[8], csh[8];
#pragma unroll
    for (int nt = 0; nt < 8; nt++) { csl[nt] = 0.0f; csh[nt] = 0.0f; }

#pragma unroll
    for (int mt = 0; mt < 4; mt++) {
        float rs0 = 0.0f, rs1 = 0.0f;
#pragma unroll
        for (int nt = 0; nt < 8; nt++) {
            float e0 = __expf(acc[mt][nt][0] - SHIFT);
            float e1 = __expf(acc[mt][nt][1] - SHIFT);
            float e2 = __expf(acc[mt][nt][2] - SHIFT);
            float e3 = __expf(acc[mt][nt][3] - SHIFT);
            rs0 += e0 + e1;
            rs1 += e2 + e3;
            csl[nt] += e0 + e2;
            csh[nt] += e1 + e3;
        }
        rs0 += __shfl_xor_sync(0xffffffffu, rs0, 1);
        rs0 += __shfl_xor_sync(0xffffffffu, rs0, 2);
        rs1 += __shfl_xor_sync(0xffffffffu, rs1, 1);
        rs1 += __shfl_xor_sync(0xffffffffu, rs1, 2);
        if ((lane & 3) == 0) {
            int row = bi * 128 + warp_m * 64 + mt * 16 + (lane >> 2);
            atomicAdd(&g_row_sum[row], rs0);
            atomicAdd(&g_row_sum[row + 8], rs1);
        }
    }
#pragma unroll
    for (int nt = 0; nt < 8; nt++) {
        float cl = csl[nt], ch = csh[nt];
        cl += __shfl_xor_sync(0xffffffffu, cl, 4);
        cl += __shfl_xor_sync(0xffffffffu, cl, 8);
        cl += __shfl_xor_sync(0xffffffffu, cl, 16);
        ch += __shfl_xor_sync(0xffffffffu, ch, 4);
        ch += __shfl_xor_sync(0xffffffffu, ch, 8);
        ch += __shfl_xor_sync(0xffffffffu, ch, 16);
        if (lane < 4) {
            int col = bj * 128 + warp_n * 64 + nt * 8 + 2 * lane;
            atomicAdd(&g_col_sum[col], cl);
            atomicAdd(&g_col_sum[col + 1], ch);
        }
    }
}

// Parallel finalize: one element per thread, 64 blocks.
__global__ void infonce_finalize_partial(float* /*unused*/) {
    __shared__ double s[256];
    int tid = threadIdx.x;
    int i = blockIdx.x * 256 + tid;
    double lse_r = (double)logf(g_row_sum[i]) + (double)SHIFT;
    double lse_c = (double)logf(g_col_sum[i]) + (double)SHIFT;
    s[tid] = 0.5 * (lse_r + lse_c) - (double)g_diag[i];
    __syncthreads();
    for (int st = 128; st > 0; st >>= 1) {
        if (tid < st) s[tid] += s[tid + st];
        __syncthreads();
    }
    if (tid == 0) atomicAdd(&g_acc, s[0]);
}

__global__ void infonce_finalize_write(float* out) {
    out[0] = (float)(g_acc / (double)NT);
}

extern "C" void kernel_launch(void* const* d_in, const int* in_sizes, int n_in,
                              void* d_out, int out_size) {
    const float* image_emb = (const float*)d_in[0];
    const float* text_emb  = (const float*)d_in[1];
    float* out = (float*)d_out;

    cudaFuncSetAttribute(infonce_mma_kernel,
                         cudaFuncAttributeMaxDynamicSharedMemorySize, 65536);

    infonce_prep_diag_kernel<<<NT * 32 / 256, 256>>>(image_emb, text_emb);
    infonce_mma_kernel<<<dim3(128, 128), 128, 65536>>>();
    infonce_finalize_partial<<<64, 256>>>(out);
    infonce_finalize_write<<<1, 1>>>(out);
}